// round 3
// baseline (speedup 1.0000x reference)
#include <cuda_runtime.h>
#include <cuda_fp16.h>
#include <cstdint>
#include <cstddef>

#define BATCH 4
#define NDIM  4096
#define CDIM  256
#define NHOP  3

// ---------------- static device scratch ----------------
__device__ float  g_bhA [(size_t)BATCH * NDIM * NDIM];   // bh3 fp32 (written by power1)
__device__ __half g_bhhA[(size_t)BATCH * NDIM * NDIM];   // b0 fp16
__device__ __half g_bhhB[(size_t)BATCH * NDIM * NDIM];   // bh2 fp16 (written by power0)
__device__ __half g_b0t [(size_t)BATCH * NDIM * NDIM];   // b0^T fp16
__device__ __half g_P   [(size_t)BATCH * NDIM * NDIM];   // softmax probs fp16
__device__ __half g_M   [(size_t)BATCH * CDIM * NDIM];   // conv_w @ nodes fp16

// ---------------- helpers ----------------
__device__ __forceinline__ uint32_t smem_u32(const void* p) {
    uint32_t a;
    asm("{ .reg .u64 t; cvta.to.shared.u64 t, %1; cvt.u32.u64 %0, t; }" : "=r"(a) : "l"(p));
    return a;
}
__device__ __forceinline__ void cp16(uint32_t dst, const void* src) {
    asm volatile("cp.async.cg.shared.global [%0], [%1], 16;" :: "r"(dst), "l"(src) : "memory");
}
__device__ __forceinline__ void ldsm4a(uint32_t& r0, uint32_t& r1, uint32_t& r2, uint32_t& r3,
                                       uint32_t addr)
{
    asm volatile("ldmatrix.sync.aligned.m8n8.x4.shared.b16 {%0,%1,%2,%3}, [%4];\n"
                 : "=r"(r0), "=r"(r1), "=r"(r2), "=r"(r3) : "r"(addr));
}
__device__ __forceinline__ void mma16816(float* d, const uint32_t* a, uint32_t b0, uint32_t b1)
{
    asm volatile("mma.sync.aligned.m16n8k16.row.col.f32.f16.f16.f32 "
                 "{%0,%1,%2,%3}, {%4,%5,%6,%7}, {%8,%9}, {%0,%1,%2,%3};\n"
                 : "+f"(d[0]), "+f"(d[1]), "+f"(d[2]), "+f"(d[3])
                 : "r"(a[0]), "r"(a[1]), "r"(a[2]), "r"(a[3]), "r"(b0), "r"(b1));
}

// ---------------- binarize + transpose (fp16 b0, fp16 b0^T) ----------------
__global__ __launch_bounds__(256) void binarize_kernel(const float* __restrict__ W,
                                                       const float* __restrict__ delta_p)
{
    __shared__ __half tile[32][33];
    const float delta = delta_p[0];
    const int b  = blockIdx.z;
    const int i0 = blockIdx.y << 5;
    const int j0 = blockIdx.x << 5;
    const size_t base = (size_t)b * NDIM * NDIM;
    const int tx = threadIdx.x, ty = threadIdx.y;

#pragma unroll
    for (int p = 0; p < 4; p++) {
        const int i = i0 + ty + p * 8;
        const size_t idx = base + (size_t)i * NDIM + (j0 + tx);
        float w  = W[idx];
        float sg = 1.0f / (1.0f + expf(-w));
        float v  = (sg - delta >= 0.0f) ? 1.0f : 0.0f;
        __half hv = __float2half_rn(v);
        g_bhhA[idx] = hv;
        tile[ty + p * 8][tx] = hv;
    }
    __syncthreads();
#pragma unroll
    for (int p = 0; p < 4; p++) {
        const int jj = ty + p * 8;
        g_b0t[base + (size_t)(j0 + jj) * NDIM + (i0 + tx)] = tile[tx][jj];
    }
}

// ---------------- row softmax, fp32-bh variant ----------------
__global__ __launch_bounds__(256) void softmax_f32(const float* __restrict__ bh,
                                                   const float* __restrict__ W,
                                                   __half* __restrict__ P)
{
    const size_t row = blockIdx.x;
    const float4* b4 = reinterpret_cast<const float4*>(bh + row * NDIM);
    const float4* w4 = reinterpret_cast<const float4*>(W  + row * NDIM);
    const int t = threadIdx.x;

    float s[16];
#pragma unroll
    for (int q = 0; q < 4; q++) {
        float4 bb = b4[t * 4 + q];
        float4 ww = w4[t * 4 + q];
        s[q * 4 + 0] = bb.x * ww.x; s[q * 4 + 1] = bb.y * ww.y;
        s[q * 4 + 2] = bb.z * ww.z; s[q * 4 + 3] = bb.w * ww.w;
    }
    float m = s[0];
#pragma unroll
    for (int k = 1; k < 16; k++) m = fmaxf(m, s[k]);
    __shared__ float red[8];
#pragma unroll
    for (int off = 16; off; off >>= 1) m = fmaxf(m, __shfl_xor_sync(0xffffffffu, m, off));
    if ((t & 31) == 0) red[t >> 5] = m;
    __syncthreads();
    m = red[0];
#pragma unroll
    for (int k = 1; k < 8; k++) m = fmaxf(m, red[k]);
    __syncthreads();
    float sum = 0.0f;
#pragma unroll
    for (int k = 0; k < 16; k++) { s[k] = __expf(s[k] - m); sum += s[k]; }
#pragma unroll
    for (int off = 16; off; off >>= 1) sum += __shfl_xor_sync(0xffffffffu, sum, off);
    if ((t & 31) == 0) red[t >> 5] = sum;
    __syncthreads();
    float tot = 0.0f;
#pragma unroll
    for (int k = 0; k < 8; k++) tot += red[k];
    const float inv = 1.0f / tot;

    uint4* P4 = reinterpret_cast<uint4*>((__half*)P + row * NDIM);
#pragma unroll
    for (int g = 0; g < 2; g++) {
        union { uint4 u; __half2 h[4]; } pk;
#pragma unroll
        for (int q = 0; q < 4; q++) {
            int e = g * 8 + q * 2;
            pk.h[q] = __floats2half2_rn(s[e] * inv, s[e + 1] * inv);
        }
        P4[t * 2 + g] = pk.u;
    }
}

// ---------------- row softmax, fp16-bh variant (bh values are exact small ints) ----------------
__global__ __launch_bounds__(256) void softmax_f16(const __half* __restrict__ bh,
                                                   const float* __restrict__ W,
                                                   __half* __restrict__ P)
{
    const size_t row = blockIdx.x;
    const uint4*  b8 = reinterpret_cast<const uint4*>(bh + row * NDIM);
    const float4* w4 = reinterpret_cast<const float4*>(W  + row * NDIM);
    const int t = threadIdx.x;

    float s[16];
#pragma unroll
    for (int g = 0; g < 2; g++) {
        union { uint4 u; __half2 h[4]; } bb;
        bb.u = b8[t * 2 + g];
#pragma unroll
        for (int q = 0; q < 4; q++) {
            float4 ww = w4[t * 4 + g * 2 + (q >> 1)];
            float2 bf = __half22float2(bb.h[q]);
            float wx = (q & 1) ? ww.z : ww.x;
            float wy = (q & 1) ? ww.w : ww.y;
            s[g * 8 + q * 2 + 0] = bf.x * wx;
            s[g * 8 + q * 2 + 1] = bf.y * wy;
        }
    }
    float m = s[0];
#pragma unroll
    for (int k = 1; k < 16; k++) m = fmaxf(m, s[k]);
    __shared__ float red[8];
#pragma unroll
    for (int off = 16; off; off >>= 1) m = fmaxf(m, __shfl_xor_sync(0xffffffffu, m, off));
    if ((t & 31) == 0) red[t >> 5] = m;
    __syncthreads();
    m = red[0];
#pragma unroll
    for (int k = 1; k < 8; k++) m = fmaxf(m, red[k]);
    __syncthreads();
    float sum = 0.0f;
#pragma unroll
    for (int k = 0; k < 16; k++) { s[k] = __expf(s[k] - m); sum += s[k]; }
#pragma unroll
    for (int off = 16; off; off >>= 1) sum += __shfl_xor_sync(0xffffffffu, sum, off);
    if ((t & 31) == 0) red[t >> 5] = sum;
    __syncthreads();
    float tot = 0.0f;
#pragma unroll
    for (int k = 0; k < 8; k++) tot += red[k];
    const float inv = 1.0f / tot;

    uint4* P4 = reinterpret_cast<uint4*>((__half*)P + row * NDIM);
#pragma unroll
    for (int g = 0; g < 2; g++) {
        union { uint4 u; __half2 h[4]; } pk;
#pragma unroll
        for (int q = 0; q < 4; q++) {
            int e = g * 8 + q * 2;
            pk.h[q] = __floats2half2_rn(s[e] * inv, s[e + 1] * inv);
        }
        P4[t * 2 + g] = pk.u;
    }
}

// ---------------- M = conv_w[hop] @ nodes[b] ----------------
__global__ __launch_bounds__(256) void convmix_kernel(const float* __restrict__ nodes,
                                                      const float* __restrict__ cw)
{
    __shared__ float scw[32][CDIM];
    const int b  = blockIdx.z;
    const int o0 = blockIdx.y * 32;
    const int i0 = blockIdx.x * 512;
    const int t  = threadIdx.x;

    for (int idx = t; idx < 32 * CDIM; idx += 256)
        scw[idx >> 8][idx & 255] = cw[(o0 + (idx >> 8)) * CDIM + (idx & 255)];
    __syncthreads();

    const int i1 = i0 + t, i2 = i0 + 256 + t;
    float acc1[32], acc2[32];
#pragma unroll
    for (int oo = 0; oo < 32; oo++) { acc1[oo] = 0.f; acc2[oo] = 0.f; }

    const float* np = nodes + (size_t)b * CDIM * NDIM;
#pragma unroll 4
    for (int c = 0; c < CDIM; c++) {
        float n1 = np[(size_t)c * NDIM + i1];
        float n2 = np[(size_t)c * NDIM + i2];
#pragma unroll
        for (int oo = 0; oo < 32; oo++) {
            float w = scw[oo][c];
            acc1[oo] += w * n1;
            acc2[oo] += w * n2;
        }
    }
    __half* mp = g_M + (size_t)b * CDIM * NDIM;
#pragma unroll
    for (int oo = 0; oo < 32; oo++) {
        mp[(size_t)(o0 + oo) * NDIM + i1] = __float2half_rn(acc1[oo]);
        mp[(size_t)(o0 + oo) * NDIM + i2] = __float2half_rn(acc2[oo]);
    }
}

// ---------------- pipelined mma.sync power GEMM: C = A @ B^T ----------------
// CTA tile 128(M) x 256(N) x 32(K), 8 warps (2x4), warp tile 64x64, 4-stage cp.async
#define P_ASTRIDE 80u                    // bytes per A/B smem row (32 halfs + pad)
#define P_AOFF    0u
#define P_BOFF    10240u                 // 128*80
#define P_STAGE   30720u                 // 128*80 + 256*80
#define P_SMEM    (4 * 30720)            // 122880

template <bool F16OUT>
__global__ __launch_bounds__(256, 1) void power_gemm(const __half* __restrict__ Ag,
                                                     const __half* __restrict__ Bg,
                                                     float*  __restrict__ Cf,
                                                     __half* __restrict__ Ch)
{
    extern __shared__ char dsm[];
    const uint32_t sbase = smem_u32(dsm);

    const int tid = threadIdx.x, wid = tid >> 5, lane = tid & 31;
    const int wm = wid & 1, wn = wid >> 1;      // warp grid 2 x 4
    const int b = blockIdx.z;
    const size_t mat = (size_t)NDIM * NDIM;
    const __half* A = Ag + (size_t)b * mat + (size_t)(blockIdx.y * 128) * NDIM;
    const __half* B = Bg + (size_t)b * mat + (size_t)(blockIdx.x * 256) * NDIM;

    const int pr = tid >> 2;       // 0..63
    const int pc = tid & 3;        // 16B chunk 0..3

    // ---- stage loader ----
    auto load_stage = [&](int kt, int s) {
        const uint32_t st = sbase + (uint32_t)s * P_STAGE;
        const __half* ag = A + kt * 32;
        const __half* bg = B + kt * 32;
#pragma unroll
        for (int i = 0; i < 2; i++) {           // A: 128 rows x 4 chunks = 512
            int r = pr + i * 64;
            cp16(st + P_AOFF + r * P_ASTRIDE + pc * 16, ag + (size_t)r * NDIM + pc * 8);
        }
#pragma unroll
        for (int i = 0; i < 4; i++) {           // B: 256 rows x 4 chunks = 1024
            int r = pr + i * 64;
            cp16(st + P_BOFF + r * P_ASTRIDE + pc * 16, bg + (size_t)r * NDIM + pc * 8);
        }
        asm volatile("cp.async.commit_group;" ::: "memory");
    };

    const int NKT = NDIM / 32;    // 128
#pragma unroll
    for (int s = 0; s < 3; s++) load_stage(s, s);

    float acc[4][8][4];
#pragma unroll
    for (int a = 0; a < 4; a++)
#pragma unroll
        for (int c = 0; c < 8; c++)
#pragma unroll
            for (int d = 0; d < 4; d++) acc[a][c][d] = 0.f;

    const uint32_t lrow16 = (lane & 15);
    const uint32_t lseg   = (lane >> 4) * 16;   // byte offset of 8-half segment

    for (int kt = 0; kt < NKT; kt++) {
        if (kt < NKT - 2)      asm volatile("cp.async.wait_group 2;" ::: "memory");
        else if (kt == NKT - 2) asm volatile("cp.async.wait_group 1;" ::: "memory");
        else                    asm volatile("cp.async.wait_group 0;" ::: "memory");
        __syncthreads();

        if (kt + 3 < NKT) load_stage(kt + 3, (kt + 3) & 3);

        const uint32_t st = sbase + (uint32_t)(kt & 3) * P_STAGE;
        const uint32_t abase = st + P_AOFF + (wm * 64 + lrow16) * P_ASTRIDE;
        const uint32_t bbase = st + P_BOFF + (wn * 64 + lrow16) * P_ASTRIDE;

#pragma unroll
        for (int ks = 0; ks < 2; ks++) {
            uint32_t afr[4][4], bfr[4][4];
#pragma unroll
            for (int mi = 0; mi < 4; mi++)
                ldsm4a(afr[mi][0], afr[mi][1], afr[mi][2], afr[mi][3],
                       abase + mi * 16 * P_ASTRIDE + ks * 32 + lseg);
#pragma unroll
            for (int nb = 0; nb < 4; nb++)
                ldsm4a(bfr[nb][0], bfr[nb][1], bfr[nb][2], bfr[nb][3],
                       bbase + nb * 16 * P_ASTRIDE + ks * 32 + lseg);
#pragma unroll
            for (int mi = 0; mi < 4; mi++)
#pragma unroll
                for (int nb = 0; nb < 4; nb++) {
                    mma16816(acc[mi][nb * 2 + 0], afr[mi], bfr[nb][0], bfr[nb][2]);
                    mma16816(acc[mi][nb * 2 + 1], afr[mi], bfr[nb][1], bfr[nb][3]);
                }
        }
    }

    // ---- epilogue ----
    const int g = lane >> 2, tq = lane & 3;
    const int brow = blockIdx.y * 128, bcol = blockIdx.x * 256;
#pragma unroll
    for (int mi = 0; mi < 4; mi++) {
        const int row_a = brow + wm * 64 + mi * 16 + g;
        const int row_b = row_a + 8;
#pragma unroll
        for (int ni = 0; ni < 8; ni++) {
            const int col = bcol + wn * 64 + ni * 8 + tq * 2;
            if (F16OUT) {
                *reinterpret_cast<__half2*>(Ch + (size_t)b * mat + (size_t)row_a * NDIM + col) =
                    __floats2half2_rn(acc[mi][ni][0], acc[mi][ni][1]);
                *reinterpret_cast<__half2*>(Ch + (size_t)b * mat + (size_t)row_b * NDIM + col) =
                    __floats2half2_rn(acc[mi][ni][2], acc[mi][ni][3]);
            } else {
                *reinterpret_cast<float2*>(Cf + (size_t)b * mat + (size_t)row_a * NDIM + col) =
                    make_float2(acc[mi][ni][0], acc[mi][ni][1]);
                *reinterpret_cast<float2*>(Cf + (size_t)b * mat + (size_t)row_b * NDIM + col) =
                    make_float2(acc[mi][ni][2], acc[mi][ni][3]);
            }
        }
    }
}

// ---------------- mma.sync NT GEMM (small out-GEMM) ----------------
__device__ __forceinline__ void ldsm4(uint32_t& r0, uint32_t& r1, uint32_t& r2, uint32_t& r3,
                                      const void* p)
{
    uint32_t addr = (uint32_t)__cvta_generic_to_shared(p);
    asm volatile("ldmatrix.sync.aligned.m8n8.x4.shared.b16 {%0,%1,%2,%3}, [%4];\n"
                 : "=r"(r0), "=r"(r1), "=r"(r2), "=r"(r3) : "r"(addr));
}

__global__ __launch_bounds__(256, 2) void gemm_nt(const __half* __restrict__ A,
                                                  const __half* __restrict__ B,
                                                  float*  __restrict__ Cf,
                                                  const float* __restrict__ bias,
                                                  int M, int Nn, int K,
                                                  size_t sA, size_t sB, size_t sC)
{
    __shared__ __half As[128][40];
    __shared__ __half Bs[128][40];

    const int bz = blockIdx.z;
    A += (size_t)bz * sA;
    B += (size_t)bz * sB;
    const size_t cbase = (size_t)bz * sC;

    const int tid  = threadIdx.x;
    const int warp = tid >> 5, lane = tid & 31;
    const int wm = warp & 3, wn = warp >> 2;
    const int brow = blockIdx.y * 128, bcol = blockIdx.x * 128;

    float acc[2][8][4];
#pragma unroll
    for (int a = 0; a < 2; a++)
#pragma unroll
        for (int b = 0; b < 8; b++)
#pragma unroll
            for (int c = 0; c < 4; c++) acc[a][b][c] = 0.f;

    const int nk = K >> 5;
    const int lr = tid >> 2;
    const int lc = (tid & 3) * 8;

    int4 ra[2], rb[2];
#pragma unroll
    for (int p = 0; p < 2; p++) {
        ra[p] = *reinterpret_cast<const int4*>(A + (size_t)(brow + p * 64 + lr) * K + lc);
        rb[p] = *reinterpret_cast<const int4*>(B + (size_t)(bcol + p * 64 + lr) * K + lc);
    }
#pragma unroll
    for (int p = 0; p < 2; p++) {
        *reinterpret_cast<int4*>(&As[p * 64 + lr][lc]) = ra[p];
        *reinterpret_cast<int4*>(&Bs[p * 64 + lr][lc]) = rb[p];
    }
    __syncthreads();

    for (int kt = 0; kt < nk; kt++) {
        if (kt + 1 < nk) {
            const int kk = (kt + 1) * 32;
#pragma unroll
            for (int p = 0; p < 2; p++) {
                ra[p] = *reinterpret_cast<const int4*>(A + (size_t)(brow + p * 64 + lr) * K + kk + lc);
                rb[p] = *reinterpret_cast<const int4*>(B + (size_t)(bcol + p * 64 + lr) * K + kk + lc);
            }
        }
#pragma unroll
        for (int ks = 0; ks < 2; ks++) {
            uint32_t afr[2][4];
#pragma unroll
            for (int mi = 0; mi < 2; mi++)
                ldsm4(afr[mi][0], afr[mi][1], afr[mi][2], afr[mi][3],
                      &As[wm * 32 + mi * 16 + (lane & 15)][ks * 16 + ((lane >> 4) << 3)]);
            uint32_t bfr[4][4];
#pragma unroll
            for (int nb = 0; nb < 4; nb++)
                ldsm4(bfr[nb][0], bfr[nb][1], bfr[nb][2], bfr[nb][3],
                      &Bs[wn * 64 + nb * 16 + (lane & 15)][ks * 16 + ((lane >> 4) << 3)]);
#pragma unroll
            for (int mi = 0; mi < 2; mi++)
#pragma unroll
                for (int nb = 0; nb < 4; nb++) {
                    mma16816(acc[mi][nb * 2 + 0], afr[mi], bfr[nb][0], bfr[nb][2]);
                    mma16816(acc[mi][nb * 2 + 1], afr[mi], bfr[nb][1], bfr[nb][3]);
                }
        }
        if (kt + 1 < nk) {
            __syncthreads();
#pragma unroll
            for (int p = 0; p < 2; p++) {
                *reinterpret_cast<int4*>(&As[p * 64 + lr][lc]) = ra[p];
                *reinterpret_cast<int4*>(&Bs[p * 64 + lr][lc]) = rb[p];
            }
            __syncthreads();
        }
    }

    const int g = lane >> 2, tq = lane & 3;
#pragma unroll
    for (int mi = 0; mi < 2; mi++) {
        const int row_a = brow + wm * 32 + mi * 16 + g;
        const int row_b = row_a + 8;
        const float bva = bias ? bias[row_a] : 0.f;
        const float bvb = bias ? bias[row_b] : 0.f;
#pragma unroll
        for (int ni = 0; ni < 8; ni++) {
            const int col = bcol + wn * 64 + ni * 8 + tq * 2;
            float v0 = acc[mi][ni][0] + bva;
            float v1 = acc[mi][ni][1] + bva;
            float v2 = acc[mi][ni][2] + bvb;
            float v3 = acc[mi][ni][3] + bvb;
            *reinterpret_cast<float2*>(Cf + cbase + (size_t)row_a * Nn + col) = make_float2(v0, v1);
            *reinterpret_cast<float2*>(Cf + cbase + (size_t)row_b * Nn + col) = make_float2(v2, v3);
        }
    }
}

// ---------------- launch ----------------
extern "C" void kernel_launch(void* const* d_in, const int* in_sizes, int n_in,
                              void* d_out, int out_size)
{
    const float* W      = (const float*)d_in[0];
    const float* nodes  = (const float*)d_in[1];
    const float* delta  = (const float*)d_in[2];
    const float* conv_w = (const float*)d_in[3];
    const float* conv_b = (const float*)d_in[4];
    float* out = (float*)d_out;

    float  *bhA;
    __half *bhhA, *bhhB, *b0t, *P, *Mh;
    cudaGetSymbolAddress((void**)&bhA,  g_bhA);
    cudaGetSymbolAddress((void**)&bhhA, g_bhhA);
    cudaGetSymbolAddress((void**)&bhhB, g_bhhB);
    cudaGetSymbolAddress((void**)&b0t,  g_b0t);
    cudaGetSymbolAddress((void**)&P,    g_P);
    cudaGetSymbolAddress((void**)&Mh,   g_M);

    cudaFuncSetAttribute(power_gemm<true>,  cudaFuncAttributeMaxDynamicSharedMemorySize, P_SMEM);
    cudaFuncSetAttribute(power_gemm<false>, cudaFuncAttributeMaxDynamicSharedMemorySize, P_SMEM);

    const size_t matS = (size_t)NDIM * NDIM;
    const size_t mS   = (size_t)CDIM * NDIM;

    binarize_kernel<<<dim3(128, 128, BATCH), dim3(32, 8)>>>(W, delta);

    for (int hop = 0; hop < NHOP; hop++) {
        convmix_kernel<<<dim3(8, 8, BATCH), 256>>>(nodes, conv_w + hop * CDIM * CDIM);

        if (hop == 0)      softmax_f16<<<BATCH * NDIM, 256>>>(bhhA, W, P);
        else if (hop == 1) softmax_f16<<<BATCH * NDIM, 256>>>(bhhB, W, P);
        else               softmax_f32<<<BATCH * NDIM, 256>>>(bhA,  W, P);

        gemm_nt<<<dim3(32, 2, BATCH), 256>>>(Mh, P,
                                             out + (size_t)hop * BATCH * CDIM * NDIM,
                                             conv_b + hop * CDIM,
                                             CDIM, NDIM, NDIM, mS, matS, mS);

        if (hop == 0)
            power_gemm<true><<<dim3(16, 32, BATCH), 256, P_SMEM>>>(bhhA, b0t, nullptr, bhhB);
        else if (hop == 1)
            power_gemm<false><<<dim3(16, 32, BATCH), 256, P_SMEM>>>(bhhB, b0t, bhA, nullptr);
    }
}

// round 4
// speedup vs baseline: 1.2570x; 1.2570x over previous
#include <cuda_runtime.h>
#include <cuda_fp16.h>
#include <cstdint>
#include <cstddef>

#define BATCH 4
#define NDIM  4096
#define CDIM  256
#define NHOP  3

// ---------------- static device scratch ----------------
__device__ float  g_bh3 [(size_t)BATCH * NDIM * NDIM];          // bh3 fp32 (power1 out)
__device__ __half g_bh2 [(size_t)BATCH * NDIM * NDIM];          // bh2 fp16 exact (power0 out)
__device__ __half g_b0th[(size_t)BATCH * NDIM * NDIM];          // b0^T fp16 (power1 B)
__device__ signed char g_b0s [(size_t)BATCH * NDIM * NDIM];     // b0 s8  (power0 A)
__device__ signed char g_b0ts[(size_t)BATCH * NDIM * NDIM];     // b0^T s8 (power0 B)
__device__ __half g_P   [(size_t)BATCH * NDIM * NDIM];          // softmax probs fp16
__device__ __half g_M   [(size_t)NHOP * BATCH * CDIM * NDIM];   // conv_w @ nodes fp16

// ---------------- helpers ----------------
__device__ __forceinline__ uint32_t smem_u32(const void* p) {
    uint32_t a;
    asm("{ .reg .u64 t; cvta.to.shared.u64 t, %1; cvt.u32.u64 %0, t; }" : "=r"(a) : "l"(p));
    return a;
}
__device__ __forceinline__ void cp16(uint32_t dst, const void* src) {
    asm volatile("cp.async.cg.shared.global [%0], [%1], 16;" :: "r"(dst), "l"(src) : "memory");
}
__device__ __forceinline__ void ldsm4a(uint32_t& r0, uint32_t& r1, uint32_t& r2, uint32_t& r3,
                                       uint32_t addr)
{
    asm volatile("ldmatrix.sync.aligned.m8n8.x4.shared.b16 {%0,%1,%2,%3}, [%4];\n"
                 : "=r"(r0), "=r"(r1), "=r"(r2), "=r"(r3) : "r"(addr));
}
__device__ __forceinline__ void mma16816(float* d, const uint32_t* a, uint32_t b0, uint32_t b1)
{
    asm volatile("mma.sync.aligned.m16n8k16.row.col.f32.f16.f16.f32 "
                 "{%0,%1,%2,%3}, {%4,%5,%6,%7}, {%8,%9}, {%0,%1,%2,%3};\n"
                 : "+f"(d[0]), "+f"(d[1]), "+f"(d[2]), "+f"(d[3])
                 : "r"(a[0]), "r"(a[1]), "r"(a[2]), "r"(a[3]), "r"(b0), "r"(b1));
}
__device__ __forceinline__ void mma_s8(int* d, const uint32_t* a, uint32_t b0, uint32_t b1)
{
    asm volatile("mma.sync.aligned.m16n8k32.row.col.s32.s8.s8.s32 "
                 "{%0,%1,%2,%3}, {%4,%5,%6,%7}, {%8,%9}, {%0,%1,%2,%3};\n"
                 : "+r"(d[0]), "+r"(d[1]), "+r"(d[2]), "+r"(d[3])
                 : "r"(a[0]), "r"(a[1]), "r"(a[2]), "r"(a[3]), "r"(b0), "r"(b1));
}

// ---------------- binarize: W -> b0 s8, b0^T s8, b0^T fp16 ----------------
__global__ __launch_bounds__(256) void binarize_kernel(const float* __restrict__ W,
                                                       const float* __restrict__ delta_p)
{
    __shared__ signed char tile[32][33];
    const float delta = delta_p[0];
    const int b  = blockIdx.z;
    const int i0 = blockIdx.y << 5;
    const int j0 = blockIdx.x << 5;
    const size_t base = (size_t)b * NDIM * NDIM;
    const int tx = threadIdx.x, ty = threadIdx.y;

#pragma unroll
    for (int p = 0; p < 4; p++) {
        const int i = i0 + ty + p * 8;
        const size_t idx = base + (size_t)i * NDIM + (j0 + tx);
        float w  = W[idx];
        float sg = 1.0f / (1.0f + expf(-w));
        signed char m = (sg - delta >= 0.0f) ? 1 : 0;
        g_b0s[idx] = m;
        tile[ty + p * 8][tx] = m;
    }
    __syncthreads();
#pragma unroll
    for (int p = 0; p < 4; p++) {
        const int jj = ty + p * 8;
        const size_t tidx = base + (size_t)(j0 + jj) * NDIM + (i0 + tx);
        signed char mv = tile[tx][jj];
        g_b0ts[tidx] = mv;
        g_b0th[tidx] = __float2half_rn((float)mv);
    }
}

// ---------------- softmax body macro (score array s[16] prepared by caller) ----------------
#define SOFTMAX_TAIL(P)                                                                   \
    float m = s[0];                                                                       \
    _Pragma("unroll") for (int k = 1; k < 16; k++) m = fmaxf(m, s[k]);                    \
    __shared__ float red[8];                                                              \
    _Pragma("unroll") for (int off = 16; off; off >>= 1)                                  \
        m = fmaxf(m, __shfl_xor_sync(0xffffffffu, m, off));                               \
    if ((t & 31) == 0) red[t >> 5] = m;                                                   \
    __syncthreads();                                                                      \
    m = red[0];                                                                           \
    _Pragma("unroll") for (int k = 1; k < 8; k++) m = fmaxf(m, red[k]);                   \
    __syncthreads();                                                                      \
    float sum = 0.0f;                                                                     \
    _Pragma("unroll") for (int k = 0; k < 16; k++) { s[k] = __expf(s[k] - m); sum += s[k]; } \
    _Pragma("unroll") for (int off = 16; off; off >>= 1)                                  \
        sum += __shfl_xor_sync(0xffffffffu, sum, off);                                    \
    if ((t & 31) == 0) red[t >> 5] = sum;                                                 \
    __syncthreads();                                                                      \
    float tot = 0.0f;                                                                     \
    _Pragma("unroll") for (int k = 0; k < 8; k++) tot += red[k];                          \
    const float inv = 1.0f / tot;                                                         \
    uint4* P4 = reinterpret_cast<uint4*>((__half*)(P) + row * NDIM);                      \
    _Pragma("unroll") for (int g = 0; g < 2; g++) {                                       \
        union { uint4 u; __half2 h[4]; } pk;                                              \
        _Pragma("unroll") for (int q = 0; q < 4; q++) {                                   \
            int e = g * 8 + q * 2;                                                        \
            pk.h[q] = __floats2half2_rn(s[e] * inv, s[e + 1] * inv);                      \
        }                                                                                 \
        P4[t * 2 + g] = pk.u;                                                             \
    }

// hop0: mask computed from W directly
__global__ __launch_bounds__(256) void softmax_mask(const float* __restrict__ W,
                                                    const float* __restrict__ delta_p,
                                                    __half* __restrict__ P)
{
    const size_t row = blockIdx.x;
    const float delta = delta_p[0];
    const float4* w4 = reinterpret_cast<const float4*>(W + row * NDIM);
    const int t = threadIdx.x;
    float s[16];
#pragma unroll
    for (int q = 0; q < 4; q++) {
        float4 ww = w4[t * 4 + q];
        float v[4] = {ww.x, ww.y, ww.z, ww.w};
#pragma unroll
        for (int e = 0; e < 4; e++) {
            float sg = 1.0f / (1.0f + expf(-v[e]));
            s[q * 4 + e] = (sg - delta >= 0.0f) ? v[e] : 0.0f;
        }
    }
    SOFTMAX_TAIL(P)
}

// hop1: bh fp16 (exact small ints)
__global__ __launch_bounds__(256) void softmax_f16(const __half* __restrict__ bh,
                                                   const float* __restrict__ W,
                                                   __half* __restrict__ P)
{
    const size_t row = blockIdx.x;
    const uint4*  b8 = reinterpret_cast<const uint4*>(bh + row * NDIM);
    const float4* w4 = reinterpret_cast<const float4*>(W  + row * NDIM);
    const int t = threadIdx.x;
    float s[16];
#pragma unroll
    for (int g = 0; g < 2; g++) {
        union { uint4 u; __half2 h[4]; } bb;
        bb.u = b8[t * 2 + g];
#pragma unroll
        for (int q = 0; q < 4; q++) {
            float4 ww = w4[t * 4 + g * 2 + (q >> 1)];
            float2 bf = __half22float2(bb.h[q]);
            float wx = (q & 1) ? ww.z : ww.x;
            float wy = (q & 1) ? ww.w : ww.y;
            s[g * 8 + q * 2 + 0] = bf.x * wx;
            s[g * 8 + q * 2 + 1] = bf.y * wy;
        }
    }
    SOFTMAX_TAIL(P)
}

// hop2: bh fp32
__global__ __launch_bounds__(256) void softmax_f32(const float* __restrict__ bh,
                                                   const float* __restrict__ W,
                                                   __half* __restrict__ P)
{
    const size_t row = blockIdx.x;
    const float4* b4 = reinterpret_cast<const float4*>(bh + row * NDIM);
    const float4* w4 = reinterpret_cast<const float4*>(W  + row * NDIM);
    const int t = threadIdx.x;
    float s[16];
#pragma unroll
    for (int q = 0; q < 4; q++) {
        float4 bb = b4[t * 4 + q];
        float4 ww = w4[t * 4 + q];
        s[q * 4 + 0] = bb.x * ww.x; s[q * 4 + 1] = bb.y * ww.y;
        s[q * 4 + 2] = bb.z * ww.z; s[q * 4 + 3] = bb.w * ww.w;
    }
    SOFTMAX_TAIL(P)
}

// ---------------- M[hop] = conv_w[hop] @ nodes[b] ----------------
__global__ __launch_bounds__(256) void convmix_kernel(const float* __restrict__ nodes,
                                                      const float* __restrict__ cw_all)
{
    __shared__ float scw[32][CDIM];
    const int hb  = blockIdx.z;             // hop*BATCH + b
    const int hop = hb >> 2, b = hb & 3;
    const int o0 = blockIdx.y * 32;
    const int i0 = blockIdx.x * 512;
    const int t  = threadIdx.x;
    const float* cw = cw_all + (size_t)hop * CDIM * CDIM;

    for (int idx = t; idx < 32 * CDIM; idx += 256)
        scw[idx >> 8][idx & 255] = cw[(o0 + (idx >> 8)) * CDIM + (idx & 255)];
    __syncthreads();

    const int i1 = i0 + t, i2 = i0 + 256 + t;
    float acc1[32], acc2[32];
#pragma unroll
    for (int oo = 0; oo < 32; oo++) { acc1[oo] = 0.f; acc2[oo] = 0.f; }

    const float* np = nodes + (size_t)b * CDIM * NDIM;
#pragma unroll 4
    for (int c = 0; c < CDIM; c++) {
        float n1 = np[(size_t)c * NDIM + i1];
        float n2 = np[(size_t)c * NDIM + i2];
#pragma unroll
        for (int oo = 0; oo < 32; oo++) {
            float w = scw[oo][c];
            acc1[oo] += w * n1;
            acc2[oo] += w * n2;
        }
    }
    __half* mp = g_M + ((size_t)hop * BATCH + b) * CDIM * NDIM;
#pragma unroll
    for (int oo = 0; oo < 32; oo++) {
        mp[(size_t)(o0 + oo) * NDIM + i1] = __float2half_rn(acc1[oo]);
        mp[(size_t)(o0 + oo) * NDIM + i2] = __float2half_rn(acc2[oo]);
    }
}

// ---------------- shared tile geometry (identical bytes for fp16 & s8) ----------------
#define P_ASTRIDE 80u
#define P_BOFF    10240u                 // 128*80
#define P_STAGE   30720u                 // (128+256)*80
#define P_SMEM    (4 * 30720)

// ---------------- s8 power GEMM: bh2 = b0 @ b0t^T, fp16 out (exact) ----------------
__global__ __launch_bounds__(256, 1) void power_s8(const signed char* __restrict__ Ag,
                                                   const signed char* __restrict__ Bg,
                                                   __half* __restrict__ Ch)
{
    extern __shared__ char dsm[];
    const uint32_t sbase = smem_u32(dsm);

    const int tid = threadIdx.x, wid = tid >> 5, lane = tid & 31;
    const int wm = wid & 1, wn = wid >> 1;
    const int b = blockIdx.z;
    const size_t mat = (size_t)NDIM * NDIM;
    const signed char* A = Ag + (size_t)b * mat + (size_t)(blockIdx.y * 128) * NDIM;
    const signed char* B = Bg + (size_t)b * mat + (size_t)(blockIdx.x * 256) * NDIM;

    const int pr = tid >> 2;
    const int pc = tid & 3;

    auto load_stage = [&](int kt, int s) {
        const uint32_t st = sbase + (uint32_t)s * P_STAGE;
        const signed char* ag = A + kt * 64;
        const signed char* bg = B + kt * 64;
#pragma unroll
        for (int i = 0; i < 2; i++) {
            int r = pr + i * 64;
            cp16(st + r * P_ASTRIDE + pc * 16, ag + (size_t)r * NDIM + pc * 16);
        }
#pragma unroll
        for (int i = 0; i < 4; i++) {
            int r = pr + i * 64;
            cp16(st + P_BOFF + r * P_ASTRIDE + pc * 16, bg + (size_t)r * NDIM + pc * 16);
        }
        asm volatile("cp.async.commit_group;" ::: "memory");
    };

    const int NKT = NDIM / 64;    // 64
#pragma unroll
    for (int s = 0; s < 3; s++) load_stage(s, s);

    int acc[4][8][4];
#pragma unroll
    for (int a = 0; a < 4; a++)
#pragma unroll
        for (int c = 0; c < 8; c++)
#pragma unroll
            for (int d = 0; d < 4; d++) acc[a][c][d] = 0;

    const uint32_t lrow16 = (lane & 15);
    const uint32_t lseg   = (lane >> 4) * 16;

    for (int kt = 0; kt < NKT; kt++) {
        if (kt < NKT - 2)       asm volatile("cp.async.wait_group 2;" ::: "memory");
        else if (kt == NKT - 2) asm volatile("cp.async.wait_group 1;" ::: "memory");
        else                    asm volatile("cp.async.wait_group 0;" ::: "memory");
        __syncthreads();

        if (kt + 3 < NKT) load_stage(kt + 3, (kt + 3) & 3);

        const uint32_t st = sbase + (uint32_t)(kt & 3) * P_STAGE;
        const uint32_t abase = st + (wm * 64 + lrow16) * P_ASTRIDE;
        const uint32_t bbase = st + P_BOFF + (wn * 64 + lrow16) * P_ASTRIDE;

#pragma unroll
        for (int ks = 0; ks < 2; ks++) {
            uint32_t afr[4][4], bfr[4][4];
#pragma unroll
            for (int mi = 0; mi < 4; mi++)
                ldsm4a(afr[mi][0], afr[mi][1], afr[mi][2], afr[mi][3],
                       abase + mi * 16 * P_ASTRIDE + ks * 32 + lseg);
#pragma unroll
            for (int nb = 0; nb < 4; nb++)
                ldsm4a(bfr[nb][0], bfr[nb][1], bfr[nb][2], bfr[nb][3],
                       bbase + nb * 16 * P_ASTRIDE + ks * 32 + lseg);
#pragma unroll
            for (int mi = 0; mi < 4; mi++)
#pragma unroll
                for (int nb = 0; nb < 4; nb++) {
                    mma_s8(acc[mi][nb * 2 + 0], afr[mi], bfr[nb][0], bfr[nb][2]);
                    mma_s8(acc[mi][nb * 2 + 1], afr[mi], bfr[nb][1], bfr[nb][3]);
                }
        }
    }

    const int g = lane >> 2, tq = lane & 3;
    const int brow = blockIdx.y * 128, bcol = blockIdx.x * 256;
#pragma unroll
    for (int mi = 0; mi < 4; mi++) {
        const int row_a = brow + wm * 64 + mi * 16 + g;
        const int row_b = row_a + 8;
#pragma unroll
        for (int ni = 0; ni < 8; ni++) {
            const int col = bcol + wn * 64 + ni * 8 + tq * 2;
            *reinterpret_cast<__half2*>(Ch + (size_t)b * mat + (size_t)row_a * NDIM + col) =
                __floats2half2_rn((float)acc[mi][ni][0], (float)acc[mi][ni][1]);
            *reinterpret_cast<__half2*>(Ch + (size_t)b * mat + (size_t)row_b * NDIM + col) =
                __floats2half2_rn((float)acc[mi][ni][2], (float)acc[mi][ni][3]);
        }
    }
}

// ---------------- fp16 power GEMM: bh3 = bh2 @ b0t^T, fp32 out ----------------
__global__ __launch_bounds__(256, 1) void power_f16(const __half* __restrict__ Ag,
                                                    const __half* __restrict__ Bg,
                                                    float* __restrict__ Cf)
{
    extern __shared__ char dsm[];
    const uint32_t sbase = smem_u32(dsm);

    const int tid = threadIdx.x, wid = tid >> 5, lane = tid & 31;
    const int wm = wid & 1, wn = wid >> 1;
    const int b = blockIdx.z;
    const size_t mat = (size_t)NDIM * NDIM;
    const __half* A = Ag + (size_t)b * mat + (size_t)(blockIdx.y * 128) * NDIM;
    const __half* B = Bg + (size_t)b * mat + (size_t)(blockIdx.x * 256) * NDIM;

    const int pr = tid >> 2;
    const int pc = tid & 3;

    auto load_stage = [&](int kt, int s) {
        const uint32_t st = sbase + (uint32_t)s * P_STAGE;
        const __half* ag = A + kt * 32;
        const __half* bg = B + kt * 32;
#pragma unroll
        for (int i = 0; i < 2; i++) {
            int r = pr + i * 64;
            cp16(st + r * P_ASTRIDE + pc * 16, ag + (size_t)r * NDIM + pc * 8);
        }
#pragma unroll
        for (int i = 0; i < 4; i++) {
            int r = pr + i * 64;
            cp16(st + P_BOFF + r * P_ASTRIDE + pc * 16, bg + (size_t)r * NDIM + pc * 8);
        }
        asm volatile("cp.async.commit_group;" ::: "memory");
    };

    const int NKT = NDIM / 32;    // 128
#pragma unroll
    for (int s = 0; s < 3; s++) load_stage(s, s);

    float acc[4][8][4];
#pragma unroll
    for (int a = 0; a < 4; a++)
#pragma unroll
        for (int c = 0; c < 8; c++)
#pragma unroll
            for (int d = 0; d < 4; d++) acc[a][c][d] = 0.f;

    const uint32_t lrow16 = (lane & 15);
    const uint32_t lseg   = (lane >> 4) * 16;

    for (int kt = 0; kt < NKT; kt++) {
        if (kt < NKT - 2)       asm volatile("cp.async.wait_group 2;" ::: "memory");
        else if (kt == NKT - 2) asm volatile("cp.async.wait_group 1;" ::: "memory");
        else                    asm volatile("cp.async.wait_group 0;" ::: "memory");
        __syncthreads();

        if (kt + 3 < NKT) load_stage(kt + 3, (kt + 3) & 3);

        const uint32_t st = sbase + (uint32_t)(kt & 3) * P_STAGE;
        const uint32_t abase = st + (wm * 64 + lrow16) * P_ASTRIDE;
        const uint32_t bbase = st + P_BOFF + (wn * 64 + lrow16) * P_ASTRIDE;

#pragma unroll
        for (int ks = 0; ks < 2; ks++) {
            uint32_t afr[4][4], bfr[4][4];
#pragma unroll
            for (int mi = 0; mi < 4; mi++)
                ldsm4a(afr[mi][0], afr[mi][1], afr[mi][2], afr[mi][3],
                       abase + mi * 16 * P_ASTRIDE + ks * 32 + lseg);
#pragma unroll
            for (int nb = 0; nb < 4; nb++)
                ldsm4a(bfr[nb][0], bfr[nb][1], bfr[nb][2], bfr[nb][3],
                       bbase + nb * 16 * P_ASTRIDE + ks * 32 + lseg);
#pragma unroll
            for (int mi = 0; mi < 4; mi++)
#pragma unroll
                for (int nb = 0; nb < 4; nb++) {
                    mma16816(acc[mi][nb * 2 + 0], afr[mi], bfr[nb][0], bfr[nb][2]);
                    mma16816(acc[mi][nb * 2 + 1], afr[mi], bfr[nb][1], bfr[nb][3]);
                }
        }
    }

    const int g = lane >> 2, tq = lane & 3;
    const int brow = blockIdx.y * 128, bcol = blockIdx.x * 256;
#pragma unroll
    for (int mi = 0; mi < 4; mi++) {
        const int row_a = brow + wm * 64 + mi * 16 + g;
        const int row_b = row_a + 8;
#pragma unroll
        for (int ni = 0; ni < 8; ni++) {
            const int col = bcol + wn * 64 + ni * 8 + tq * 2;
            *reinterpret_cast<float2*>(Cf + (size_t)b * mat + (size_t)row_a * NDIM + col) =
                make_float2(acc[mi][ni][0], acc[mi][ni][1]);
            *reinterpret_cast<float2*>(Cf + (size_t)b * mat + (size_t)row_b * NDIM + col) =
                make_float2(acc[mi][ni][2], acc[mi][ni][3]);
        }
    }
}

// ---------------- pipelined out-GEMM: out[o,i] = sum_j M[o,j] P[i,j] + bias[o] ----------------
__global__ __launch_bounds__(256, 1) void gemm_out(const __half* __restrict__ Mg,
                                                   const __half* __restrict__ Pg,
                                                   float* __restrict__ Og,
                                                   const float* __restrict__ bias)
{
    extern __shared__ char dsm[];
    const uint32_t sbase = smem_u32(dsm);

    const int tid = threadIdx.x, wid = tid >> 5, lane = tid & 31;
    const int wm = wid & 1, wn = wid >> 1;
    const int b = blockIdx.z;
    const size_t mat = (size_t)NDIM * NDIM;
    const size_t mS  = (size_t)CDIM * NDIM;
    const __half* A = Mg + (size_t)b * mS  + (size_t)(blockIdx.y * 128) * NDIM;
    const __half* B = Pg + (size_t)b * mat + (size_t)(blockIdx.x * 256) * NDIM;

    const int pr = tid >> 2;
    const int pc = tid & 3;

    auto load_stage = [&](int kt, int s) {
        const uint32_t st = sbase + (uint32_t)s * P_STAGE;
        const __half* ag = A + kt * 32;
        const __half* bg = B + kt * 32;
#pragma unroll
        for (int i = 0; i < 2; i++) {
            int r = pr + i * 64;
            cp16(st + r * P_ASTRIDE + pc * 16, ag + (size_t)r * NDIM + pc * 8);
        }
#pragma unroll
        for (int i = 0; i < 4; i++) {
            int r = pr + i * 64;
            cp16(st + P_BOFF + r * P_ASTRIDE + pc * 16, bg + (size_t)r * NDIM + pc * 8);
        }
        asm volatile("cp.async.commit_group;" ::: "memory");
    };

    const int NKT = NDIM / 32;
#pragma unroll
    for (int s = 0; s < 3; s++) load_stage(s, s);

    float acc[4][8][4];
#pragma unroll
    for (int a = 0; a < 4; a++)
#pragma unroll
        for (int c = 0; c < 8; c++)
#pragma unroll
            for (int d = 0; d < 4; d++) acc[a][c][d] = 0.f;

    const uint32_t lrow16 = (lane & 15);
    const uint32_t lseg   = (lane >> 4) * 16;

    for (int kt = 0; kt < NKT; kt++) {
        if (kt < NKT - 2)       asm volatile("cp.async.wait_group 2;" ::: "memory");
        else if (kt == NKT - 2) asm volatile("cp.async.wait_group 1;" ::: "memory");
        else                    asm volatile("cp.async.wait_group 0;" ::: "memory");
        __syncthreads();

        if (kt + 3 < NKT) load_stage(kt + 3, (kt + 3) & 3);

        const uint32_t st = sbase + (uint32_t)(kt & 3) * P_STAGE;
        const uint32_t abase = st + (wm * 64 + lrow16) * P_ASTRIDE;
        const uint32_t bbase = st + P_BOFF + (wn * 64 + lrow16) * P_ASTRIDE;

#pragma unroll
        for (int ks = 0; ks < 2; ks++) {
            uint32_t afr[4][4], bfr[4][4];
#pragma unroll
            for (int mi = 0; mi < 4; mi++)
                ldsm4a(afr[mi][0], afr[mi][1], afr[mi][2], afr[mi][3],
                       abase + mi * 16 * P_ASTRIDE + ks * 32 + lseg);
#pragma unroll
            for (int nb = 0; nb < 4; nb++)
                ldsm4a(bfr[nb][0], bfr[nb][1], bfr[nb][2], bfr[nb][3],
                       bbase + nb * 16 * P_ASTRIDE + ks * 32 + lseg);
#pragma unroll
            for (int mi = 0; mi < 4; mi++)
#pragma unroll
                for (int nb = 0; nb < 4; nb++) {
                    mma16816(acc[mi][nb * 2 + 0], afr[mi], bfr[nb][0], bfr[nb][2]);
                    mma16816(acc[mi][nb * 2 + 1], afr[mi], bfr[nb][1], bfr[nb][3]);
                }
        }
    }

    const int g = lane >> 2, tq = lane & 3;
    const int brow = blockIdx.y * 128, bcol = blockIdx.x * 256;
#pragma unroll
    for (int mi = 0; mi < 4; mi++) {
        const int row_a = brow + wm * 64 + mi * 16 + g;
        const int row_b = row_a + 8;
        const float bva = bias[row_a];
        const float bvb = bias[row_b];
#pragma unroll
        for (int ni = 0; ni < 8; ni++) {
            const int col = bcol + wn * 64 + ni * 8 + tq * 2;
            *reinterpret_cast<float2*>(Og + (size_t)b * mS + (size_t)row_a * NDIM + col) =
                make_float2(acc[mi][ni][0] + bva, acc[mi][ni][1] + bva);
            *reinterpret_cast<float2*>(Og + (size_t)b * mS + (size_t)row_b * NDIM + col) =
                make_float2(acc[mi][ni][2] + bvb, acc[mi][ni][3] + bvb);
        }
    }
}

// ---------------- launch ----------------
extern "C" void kernel_launch(void* const* d_in, const int* in_sizes, int n_in,
                              void* d_out, int out_size)
{
    const float* W      = (const float*)d_in[0];
    const float* nodes  = (const float*)d_in[1];
    const float* delta  = (const float*)d_in[2];
    const float* conv_w = (const float*)d_in[3];
    const float* conv_b = (const float*)d_in[4];
    float* out = (float*)d_out;

    float  *bh3;
    __half *bh2, *b0th, *P, *Mh;
    signed char *b0s, *b0ts;
    cudaGetSymbolAddress((void**)&bh3,  g_bh3);
    cudaGetSymbolAddress((void**)&bh2,  g_bh2);
    cudaGetSymbolAddress((void**)&b0th, g_b0th);
    cudaGetSymbolAddress((void**)&b0s,  g_b0s);
    cudaGetSymbolAddress((void**)&b0ts, g_b0ts);
    cudaGetSymbolAddress((void**)&P,    g_P);
    cudaGetSymbolAddress((void**)&Mh,   g_M);

    cudaFuncSetAttribute(power_s8,  cudaFuncAttributeMaxDynamicSharedMemorySize, P_SMEM);
    cudaFuncSetAttribute(power_f16, cudaFuncAttributeMaxDynamicSharedMemorySize, P_SMEM);
    cudaFuncSetAttribute(gemm_out,  cudaFuncAttributeMaxDynamicSharedMemorySize, P_SMEM);

    const size_t mS = (size_t)CDIM * NDIM;

    binarize_kernel<<<dim3(128, 128, BATCH), dim3(32, 8)>>>(W, delta);
    convmix_kernel<<<dim3(8, 8, NHOP * BATCH), 256>>>(nodes, conv_w);

    // hop 0
    softmax_mask<<<BATCH * NDIM, 256>>>(W, delta, P);
    gemm_out<<<dim3(16, 2, BATCH), 256, P_SMEM>>>(Mh + 0 * BATCH * mS, P,
                                                  out + 0 * BATCH * mS, conv_b + 0 * CDIM);
    power_s8<<<dim3(16, 32, BATCH), 256, P_SMEM>>>(b0s, b0ts, bh2);

    // hop 1
    softmax_f16<<<BATCH * NDIM, 256>>>(bh2, W, P);
    gemm_out<<<dim3(16, 2, BATCH), 256, P_SMEM>>>(Mh + 1 * BATCH * mS, P,
                                                  out + 1 * BATCH * mS, conv_b + 1 * CDIM);
    power_f16<<<dim3(16, 32, BATCH), 256, P_SMEM>>>(bh2, b0th, bh3);

    // hop 2
    softmax_f32<<<BATCH * NDIM, 256>>>(bh3, W, P);
    gemm_out<<<dim3(16, 2, BATCH), 256, P_SMEM>>>(Mh + 2 * BATCH * mS, P,
                                                  out + 2 * BATCH * mS, conv_b + 2 * CDIM);
}